// round 8
// baseline (speedup 1.0000x reference)
#include <cuda_runtime.h>
#include <cstdint>
#include <cstddef>

// ---------------------------------------------------------------------------
// BaseGIN: 3-layer GIN on a 100k-node / 1.6M-edge graph.
//
// Per layer (project-then-aggregate; aggregation is linear):
//   y = A_in @ Wa                      (GEMM-A, K=128 for layer 1 else 64)
//   z[n] = (1+eps)*y[n] + ba + sum_{e: dst=n} w_e * y[src_e]   (CSR gather)
//   u = relu(z) @ Wb + bb              (GEMM-B, relu fused on A-load)
//   stats: per-column sum / sumsq of u (fused into GEMM-B epilogue)
//   h' = relu((u-mean)*rsqrt(var+eps)*gamma + beta)  [+ h  for layers 2,3]
//
// R7: GEMMs rebuilt FMA-bound: 128 thr/block, 8x8 per-thread tile,
// row-major smem A (conflict-free STS.128), fewer barriers.
// ---------------------------------------------------------------------------

static constexpr int H    = 64;
static constexpr int BM   = 128;   // rows per GEMM block
static constexpr int MAXN = 131072;
static constexpr int MAXE = 1700000;
static constexpr int SCAN_EPB = 2048;            // elements per scan block

__device__ __align__(16) float g_y[MAXN * H];
__device__ __align__(16) float g_z[MAXN * H];
__device__ __align__(16) float g_u[MAXN * H];
__device__ __align__(16) float g_h[MAXN * H];
__device__ float g_stats[2 * H];
__device__ int   g_idx64;            // 1 if edge_index is int64, 0 if int32
__device__ int   g_deg[MAXN];
__device__ int   g_rowptr[MAXN + 1];
__device__ int   g_wptr[MAXN];
__device__ int   g_esrc[MAXE];
__device__ float g_ewp[MAXE];
__device__ int   g_bsum[128];        // per-block degree sums (<=64 used)

typedef unsigned long long ull;

// ---- packed f32x2 helpers (Blackwell FFMA2 is only reachable via PTX) -----
__device__ __forceinline__ ull pk2(float a, float b) {
    ull r;
    asm("mov.b64 %0, {%1,%2};" : "=l"(r) : "f"(a), "f"(b));
    return r;
}
__device__ __forceinline__ void fma2(ull& d, ull a, ull b) {
    asm("fma.rn.f32x2 %0, %1, %2, %0;" : "+l"(d) : "l"(a), "l"(b));
}
__device__ __forceinline__ float2 up2(ull v) {
    float lo, hi;
    asm("mov.b64 {%0,%1}, %2;" : "=f"(lo), "=f"(hi) : "l"(v));
    return make_float2(lo, hi);
}
__device__ __forceinline__ float fcomp(const float4& v, int kk) {
    return kk == 0 ? v.x : kk == 1 ? v.y : kk == 2 ? v.z : v.w;
}

// ---------------------------------------------------------------------------
// Detect edge_index dtype (int64 vs int32).
// ---------------------------------------------------------------------------
__global__ void detect_k(const unsigned* __restrict__ ei32) {
    int is64 = 1;
#pragma unroll
    for (int i = 0; i < 64; i++)
        if (ei32[2 * i + 1] != 0u) is64 = 0;
    g_idx64 = is64;
}

__device__ __forceinline__ long long load_idx(const void* ei, int pos) {
    return g_idx64 ? ((const long long*)ei)[pos] : (long long)((const int*)ei)[pos];
}

// ---------------------------------------------------------------------------
// CSR build: zero -> histogram -> 3-phase scan -> permuted fill
// ---------------------------------------------------------------------------
__global__ void zero_deg_k(int N) {
    int i = blockIdx.x * blockDim.x + threadIdx.x;
    if (i < N) g_deg[i] = 0;
}

__global__ void hist_k(const void* __restrict__ ei, int E, int N) {
    int e = blockIdx.x * blockDim.x + threadIdx.x;
    if (e >= E) return;
    long long d = load_idx(ei, E + e);
    if ((unsigned long long)d < (unsigned long long)N)
        atomicAdd(&g_deg[(int)d], 1);
}

__global__ __launch_bounds__(256) void scan_sum_k(int N) {
    int b = blockIdx.x, t = threadIdx.x;
    int base = b * SCAN_EPB + t * 8;
    int s = 0;
#pragma unroll
    for (int i = 0; i < 8; i++) {
        int idx = base + i;
        if (idx < N) s += g_deg[idx];
    }
    __shared__ int red[256];
    red[t] = s;
    __syncthreads();
    for (int off = 128; off > 0; off >>= 1) {
        if (t < off) red[t] += red[t + off];
        __syncthreads();
    }
    if (t == 0) g_bsum[b] = red[0];
}

__global__ __launch_bounds__(128) void scan_top_k(int nb, int N) {
    __shared__ int sh[128];
    int t = threadIdx.x;
    int v = (t < nb) ? g_bsum[t] : 0;
    sh[t] = v;
    __syncthreads();
    for (int off = 1; off < 128; off <<= 1) {
        int u = (t >= off) ? sh[t - off] : 0;
        __syncthreads();
        sh[t] += u;
        __syncthreads();
    }
    if (t < nb) g_bsum[t] = sh[t] - v;
    if (t == 127) g_rowptr[N] = sh[127];
}

__global__ __launch_bounds__(256) void scan_apply_k(int N) {
    int b = blockIdx.x, t = threadIdx.x;
    int base = b * SCAN_EPB + t * 8;
    int d[8];
    int s = 0;
#pragma unroll
    for (int i = 0; i < 8; i++) {
        int idx = base + i;
        d[i] = (idx < N) ? g_deg[idx] : 0;
        s += d[i];
    }
    __shared__ int sh[256];
    sh[t] = s;
    __syncthreads();
    for (int off = 1; off < 256; off <<= 1) {
        int u = (t >= off) ? sh[t - off] : 0;
        __syncthreads();
        sh[t] += u;
        __syncthreads();
    }
    int run = g_bsum[b] + sh[t] - s;
#pragma unroll
    for (int i = 0; i < 8; i++) {
        int idx = base + i;
        if (idx < N) { g_rowptr[idx] = run; g_wptr[idx] = run; }
        run += d[i];
    }
}

__global__ void fill_k(const void* __restrict__ ei,
                       const float* __restrict__ ew, int E, int N) {
    int e = blockIdx.x * blockDim.x + threadIdx.x;
    if (e >= E) return;
    long long s = load_idx(ei, e);
    long long d = load_idx(ei, E + e);
    if ((unsigned long long)s >= (unsigned long long)N ||
        (unsigned long long)d >= (unsigned long long)N) return;
    int pos = atomicAdd(&g_wptr[(int)d], 1);
    g_esrc[pos] = (int)s;
    g_ewp[pos]  = ew[e];
}

// ---------------------------------------------------------------------------
// GEMM core: 128 threads, per-thread 8 rows x 8 cols.
// thread: ry = tid>>3 (rows ry*8..+7), cx = tid&7 (cols cx*8..+7)
// acc[r][cp] = f32x2 over cols (cx*8+2cp, cx*8+2cp+1)
// A-tile row-major in smem (stride KC+8 floats, 16B-aligned rows):
//   store phase = conflict-free STS.128, read = quarter-warp broadcast.
// ---------------------------------------------------------------------------

// GEMM-A: y = A @ W  (A = external x for K=128, g_h for K=64)
template <int K>
__global__ __launch_bounds__(128) void gemm_a(
    const float* __restrict__ Ain, const float* __restrict__ W, int N)
{
    constexpr int KC  = (K == 64) ? 32 : 16;
    constexpr int ASW = KC + 8;                 // padded row stride (floats)
    const float* A = (K == 128) ? Ain : (const float*)g_h;
    __shared__ float Ws[K][H];
    __shared__ float As[BM][ASW];

    const int tid = threadIdx.x;
    const int ry  = tid >> 3;
    const int cx  = tid & 7;
    const int bm0 = blockIdx.x * BM;

    for (int i = tid * 4; i < K * H; i += 512)
        *(float4*)((float*)Ws + i) = *(const float4*)&W[i];

    ull acc[8][4];
#pragma unroll
    for (int r = 0; r < 8; r++)
#pragma unroll
        for (int c = 0; c < 4; c++) acc[r][c] = 0ULL;

    for (int kb = 0; kb < K; kb += KC) {
        __syncthreads();
#pragma unroll
        for (int it = 0; it < (KC * BM) / 512; it++) {
            int e  = it * 128 + tid;
            int rl = e / (KC / 4);
            int kq = (e % (KC / 4)) * 4;
            int r  = bm0 + rl;
            float4 v = make_float4(0.f, 0.f, 0.f, 0.f);
            if (r < N) v = *(const float4*)&A[(size_t)r * K + kb + kq];
            *(float4*)&As[rl][kq] = v;
        }
        __syncthreads();
#pragma unroll 4
        for (int k4 = 0; k4 < KC / 4; k4++) {
            float4 av[8];
#pragma unroll
            for (int r = 0; r < 8; r++)
                av[r] = *(float4*)&As[ry * 8 + r][k4 * 4];
#pragma unroll
            for (int kk = 0; kk < 4; kk++) {
                const float* wrow = &Ws[kb + k4 * 4 + kk][cx * 8];
                float4 w0 = *(const float4*)&wrow[0];
                float4 w1 = *(const float4*)&wrow[4];
                ull wp[4] = { pk2(w0.x, w0.y), pk2(w0.z, w0.w),
                              pk2(w1.x, w1.y), pk2(w1.z, w1.w) };
#pragma unroll
                for (int r = 0; r < 8; r++) {
                    float a = fcomp(av[r], kk);
                    ull ad = pk2(a, a);
#pragma unroll
                    for (int cp = 0; cp < 4; cp++) fma2(acc[r][cp], ad, wp[cp]);
                }
            }
        }
    }

#pragma unroll
    for (int r = 0; r < 8; r++) {
        int row = bm0 + ry * 8 + r;
        if (row >= N) continue;
        float2 p0 = up2(acc[r][0]), p1 = up2(acc[r][1]);
        float2 p2 = up2(acc[r][2]), p3 = up2(acc[r][3]);
        float* out = &g_y[(size_t)row * H + cx * 8];
        *(float4*)&out[0] = make_float4(p0.x, p0.y, p1.x, p1.y);
        *(float4*)&out[4] = make_float4(p2.x, p2.y, p3.x, p3.y);
    }
}

// GEMM-B: u = relu(z) @ W + bb ; per-column sum/sumsq into g_stats.
__global__ __launch_bounds__(128) void gemm_b(
    const float* __restrict__ W, const float* __restrict__ bb, int N)
{
    constexpr int K   = 64;
    constexpr int KC  = 32;
    constexpr int ASW = KC + 8;
    __shared__ float Ws[K][H];
    __shared__ float As[BM][ASW];
    __shared__ float red_s[2 * H];

    const int tid = threadIdx.x;
    const int ry  = tid >> 3;
    const int cx  = tid & 7;
    const int bm0 = blockIdx.x * BM;

    for (int i = tid * 4; i < K * H; i += 512)
        *(float4*)((float*)Ws + i) = *(const float4*)&W[i];

    ull acc[8][4];
#pragma unroll
    for (int r = 0; r < 8; r++)
#pragma unroll
        for (int c = 0; c < 4; c++) acc[r][c] = 0ULL;

    for (int kb = 0; kb < K; kb += KC) {
        __syncthreads();
#pragma unroll
        for (int it = 0; it < (KC * BM) / 512; it++) {
            int e  = it * 128 + tid;
            int rl = e / (KC / 4);
            int kq = (e % (KC / 4)) * 4;
            int r  = bm0 + rl;
            float4 v = make_float4(0.f, 0.f, 0.f, 0.f);
            if (r < N) {
                v = *(const float4*)&g_z[(size_t)r * K + kb + kq];
                v.x = fmaxf(v.x, 0.f); v.y = fmaxf(v.y, 0.f);
                v.z = fmaxf(v.z, 0.f); v.w = fmaxf(v.w, 0.f);
            }
            *(float4*)&As[rl][kq] = v;
        }
        __syncthreads();
#pragma unroll 4
        for (int k4 = 0; k4 < KC / 4; k4++) {
            float4 av[8];
#pragma unroll
            for (int r = 0; r < 8; r++)
                av[r] = *(float4*)&As[ry * 8 + r][k4 * 4];
#pragma unroll
            for (int kk = 0; kk < 4; kk++) {
                const float* wrow = &Ws[kb + k4 * 4 + kk][cx * 8];
                float4 w0 = *(const float4*)&wrow[0];
                float4 w1 = *(const float4*)&wrow[4];
                ull wp[4] = { pk2(w0.x, w0.y), pk2(w0.z, w0.w),
                              pk2(w1.x, w1.y), pk2(w1.z, w1.w) };
#pragma unroll
                for (int r = 0; r < 8; r++) {
                    float a = fcomp(av[r], kk);
                    ull ad = pk2(a, a);
#pragma unroll
                    for (int cp = 0; cp < 4; cp++) fma2(acc[r][cp], ad, wp[cp]);
                }
            }
        }
    }

    float4 b0 = *(const float4*)&bb[cx * 8];
    float4 b1 = *(const float4*)&bb[cx * 8 + 4];
    float s1[8] = {0, 0, 0, 0, 0, 0, 0, 0};
    float s2[8] = {0, 0, 0, 0, 0, 0, 0, 0};
#pragma unroll
    for (int r = 0; r < 8; r++) {
        int row = bm0 + ry * 8 + r;
        if (row >= N) continue;
        float2 p0 = up2(acc[r][0]), p1 = up2(acc[r][1]);
        float2 p2 = up2(acc[r][2]), p3 = up2(acc[r][3]);
        float o[8] = { p0.x + b0.x, p0.y + b0.y, p1.x + b0.z, p1.y + b0.w,
                       p2.x + b1.x, p2.y + b1.y, p3.x + b1.z, p3.y + b1.w };
        float* out = &g_u[(size_t)row * H + cx * 8];
        *(float4*)&out[0] = make_float4(o[0], o[1], o[2], o[3]);
        *(float4*)&out[4] = make_float4(o[4], o[5], o[6], o[7]);
#pragma unroll
        for (int c = 0; c < 8; c++) { s1[c] += o[c]; s2[c] += o[c] * o[c]; }
    }
    __syncthreads();
    if (tid < 2 * H) red_s[tid] = 0.f;
    __syncthreads();
#pragma unroll
    for (int c = 0; c < 8; c++) {
        atomicAdd(&red_s[cx * 8 + c], s1[c]);
        atomicAdd(&red_s[H + cx * 8 + c], s2[c]);
    }
    __syncthreads();
    if (tid < 2 * H) atomicAdd(&g_stats[tid], red_s[tid]);
}

// ---------------------------------------------------------------------------
// CSR gather: z[n] = (1+eps)*y[n] + ba + sum_e w_e * y[src_e]
// ---------------------------------------------------------------------------
__global__ __launch_bounds__(256) void gather_k(
    const float* __restrict__ ba, const float* __restrict__ eps_p, int N)
{
    if (blockIdx.x == 0 && threadIdx.x < 2 * H)
        g_stats[threadIdx.x] = 0.f;

    int t = blockIdx.x * blockDim.x + threadIdx.x;
    int n = t >> 4;
    if (n >= N) return;
    int j = (t & 15) * 4;

    int beg = g_rowptr[n];
    int end = g_rowptr[n + 1];
    float4 acc0 = make_float4(0.f, 0.f, 0.f, 0.f);
    float4 acc1 = make_float4(0.f, 0.f, 0.f, 0.f);
    int e = beg;
    for (; e + 1 < end; e += 2) {
        int   s0 = g_esrc[e],     s1 = g_esrc[e + 1];
        float w0 = g_ewp[e];
        float w1 = g_ewp[e + 1];
        float4 v0 = *(const float4*)&g_y[(size_t)s0 * H + j];
        float4 v1 = *(const float4*)&g_y[(size_t)s1 * H + j];
        acc0.x += w0 * v0.x; acc0.y += w0 * v0.y;
        acc0.z += w0 * v0.z; acc0.w += w0 * v0.w;
        acc1.x += w1 * v1.x; acc1.y += w1 * v1.y;
        acc1.z += w1 * v1.z; acc1.w += w1 * v1.w;
    }
    if (e < end) {
        int   s = g_esrc[e];
        float w = g_ewp[e];
        float4 v = *(const float4*)&g_y[(size_t)s * H + j];
        acc0.x += w * v.x; acc0.y += w * v.y;
        acc0.z += w * v.z; acc0.w += w * v.w;
    }
    acc0.x += acc1.x; acc0.y += acc1.y; acc0.z += acc1.z; acc0.w += acc1.w;

    const float ep1 = 1.0f + *eps_p;
    float4 yv  = *(const float4*)&g_y[(size_t)n * H + j];
    float4 bav = *(const float4*)&ba[j];
    float4 zv  = make_float4(fmaf(ep1, yv.x, bav.x + acc0.x),
                             fmaf(ep1, yv.y, bav.y + acc0.y),
                             fmaf(ep1, yv.z, bav.z + acc0.z),
                             fmaf(ep1, yv.w, bav.w + acc0.w));
    *(float4*)&g_z[(size_t)n * H + j] = zv;
}

// ---------------------------------------------------------------------------
// BN affine + relu (+ residual).  out = ext_out ? ext_out : g_h.
// ---------------------------------------------------------------------------
__global__ __launch_bounds__(256) void bn_apply(
    const float* __restrict__ gamma, const float* __restrict__ beta,
    int N, int residual, float* __restrict__ ext_out)
{
    __shared__ float sc[H], sh[H];
    int tid = threadIdx.x;
    if (tid < H) {
        float inv = 1.f / (float)N;
        float m   = g_stats[tid] * inv;
        float var = g_stats[H + tid] * inv - m * m;
        float s   = gamma[tid] * rsqrtf(var + 1e-5f);
        sc[tid] = s;
        sh[tid] = beta[tid] - m * s;
    }
    __syncthreads();
    int i = blockIdx.x * blockDim.x + tid;
    if (i >= N * (H / 4)) return;
    int c = (i & 15) * 4;
    float4 v = ((const float4*)g_u)[i];
    v.x = fmaxf(fmaf(v.x, sc[c + 0], sh[c + 0]), 0.f);
    v.y = fmaxf(fmaf(v.y, sc[c + 1], sh[c + 1]), 0.f);
    v.z = fmaxf(fmaf(v.z, sc[c + 2], sh[c + 2]), 0.f);
    v.w = fmaxf(fmaf(v.w, sc[c + 3], sh[c + 3]), 0.f);
    if (residual) {
        float4 p = ((const float4*)g_h)[i];
        v.x += p.x; v.y += p.y; v.z += p.z; v.w += p.w;
    }
    float4* outp = ext_out ? (float4*)ext_out : (float4*)g_h;
    outp[i] = v;
}

// ---------------------------------------------------------------------------
extern "C" void kernel_launch(void* const* d_in, const int* in_sizes, int n_in,
                              void* d_out, int out_size)
{
    const float* x    = (const float*)d_in[0];
    const void*  ei   = d_in[1];
    const float* ew   = (const float*)d_in[2];
    const float* eps1 = (const float*)d_in[3];
    const float* W1a  = (const float*)d_in[4];
    const float* b1a  = (const float*)d_in[5];
    const float* W1b  = (const float*)d_in[6];
    const float* b1b  = (const float*)d_in[7];
    const float* g1   = (const float*)d_in[8];
    const float* be1  = (const float*)d_in[9];
    const float* epss = (const float*)d_in[10];
    const float* Wsa  = (const float*)d_in[11];
    const float* bsa  = (const float*)d_in[12];
    const float* Wsb  = (const float*)d_in[13];
    const float* bsb  = (const float*)d_in[14];
    const float* gs   = (const float*)d_in[15];
    const float* bes  = (const float*)d_in[16];

    const int N  = in_sizes[0] / 128;
    const int E  = in_sizes[2];
    const int nb = (N + BM - 1) / BM;
    const int eb = (E + 255) / 256;
    const int gb = (N * 16 + 255) / 256;
    const int ub = (N * (H / 4) + 255) / 256;
    const int sb = (N + SCAN_EPB - 1) / SCAN_EPB;

    // ---- CSR build (once; reused by all 3 layers) ----
    detect_k<<<1, 1>>>((const unsigned*)ei);
    zero_deg_k<<<(N + 255) / 256, 256>>>(N);
    hist_k<<<eb, 256>>>(ei, E, N);
    scan_sum_k<<<sb, 256>>>(N);
    scan_top_k<<<1, 128>>>(sb, N);
    scan_apply_k<<<sb, 256>>>(N);
    fill_k<<<eb, 256>>>(ei, ew, E, N);

    // ---- layer 1 (K = 128) ----
    gemm_a<128><<<nb, 128>>>(x, W1a, N);
    gather_k<<<gb, 256>>>(b1a, eps1, N);
    gemm_b<<<nb, 128>>>(W1b, b1b, N);
    bn_apply<<<ub, 256>>>(g1, be1, N, 0, nullptr);

    // ---- layer 2 ----
    gemm_a<64><<<nb, 128>>>(nullptr, Wsa, N);
    gather_k<<<gb, 256>>>(bsa, epss, N);
    gemm_b<<<nb, 128>>>(Wsb, bsb, N);
    bn_apply<<<ub, 256>>>(gs, bes, N, 1, nullptr);

    // ---- layer 3 ----
    gemm_a<64><<<nb, 128>>>(nullptr, Wsa + 64 * 64, N);
    gather_k<<<gb, 256>>>(bsa + 64, epss + 1, N);
    gemm_b<<<nb, 128>>>(Wsb + 64 * 64, bsb + 64, N);
    bn_apply<<<ub, 256>>>(gs + 64, bes + 64, N, 1, (float*)d_out);
}